// round 7
// baseline (speedup 1.0000x reference)
#include <cuda_runtime.h>
#include <cstdint>

#define Hh 200
#define Ww 196
#define Cc 256
#define NCAMS 6
#define SSZ 400
#define NCELLS (SSZ*SSZ)
#define NPTS (Hh*Ww)     // 39200
#define HQ (Hh/4)        // 50
#define NSEG 8           // channel groups
#define CPG (Cc/NSEG)    // 32 channels per group
#define NTHREADS (NCAMS*Ww*NSEG*HQ)     // 470400
#define NVB ((NTHREADS + 255) / 256)    // 1838 work tiles
#define NQ (NCELLS/4)                   // 40000 float4 cells
#define CTAS_PER_SM 6                   // launch_bounds -> <=42 regs

// Zero-initialized at module load; the kernel restores all of them to zero
// before exiting, so every launch / graph replay sees zeroed scratch.
__device__ float    g_sum[NCELLS];
__device__ float    g_cnt[NCELLS];
__device__ unsigned g_bar;
__device__ unsigned g_bar2;

// Persistent kernel, 6 CTAs/SM guaranteed resident:
//  Phase 1: 1838 tiles (point-quad x 32-channel group); stream td_feats once
//           (coalesced float4 over innermost h, simple unrolled loop — R3's
//           proven codegen), partial-dot vs s_w, scatter scalar partials
//           (+count from seg 0) via L2 atomics.
//  Barrier: software grid barrier (deadlock-free: all CTAs resident).
//  Phase 2: divide / add bias / store output; reset scratch; reset barrier.
__global__ void __launch_bounds__(256, CTAS_PER_SM) fused_all_kernel(
    const float* __restrict__ td, const float* __restrict__ cam,
    const float* __restrict__ lc, const void*  __restrict__ mask,
    const float* __restrict__ wcls, const float* __restrict__ bcls,
    float* __restrict__ out)
{
    __shared__ float s_w[Cc];
    __shared__ int   s_mode;

    // Mask-dtype fingerprint (mask ~90% true) over first 384 bytes:
    //   int32 0/1 : low byte of words sometimes set, upper 3 bytes never
    //   f32 0/1.0 : low byte never, upper bytes sometimes (0x3f800000)
    //   u8 bool   : both populated
    if (threadIdx.x < 32) {
        const unsigned* mw = (const unsigned*)mask;
        unsigned lo = 0, hi = 0;
        #pragma unroll
        for (int k = 0; k < 3; ++k) {
            unsigned v = mw[threadIdx.x + 32 * k];
            lo |= (v & 0xFFu);
            hi |= (v & 0xFFFFFF00u);
        }
        unsigned any_lo = __ballot_sync(0xFFFFFFFF, lo != 0);
        unsigned any_hi = __ballot_sync(0xFFFFFFFF, hi != 0);
        if (threadIdx.x == 0) {
            int mode;
            if (any_lo && any_hi) mode = 1;   // u8 bool
            else if (any_lo)      mode = 0;   // int32
            else                  mode = 2;   // float32
            s_mode = mode;
        }
    }
    for (int i = threadIdx.x; i < Cc; i += blockDim.x) s_w[i] = wcls[i];
    __syncthreads();
    const int mode = s_mode;
    const int ch_stride4 = (Ww * Hh) / 4;   // 9800 float4 between channels

    // ---------------- Phase 1: stream + scatter ----------------
    for (int vb = blockIdx.x; vb < NVB; vb += gridDim.x) {
        int tid = vb * 256 + threadIdx.x;
        if (tid >= NTHREADS) break;
        // hq innermost for coalescing, then chan-group, then w, then cam
        int hq  = tid % HQ;
        int t2  = tid / HQ;
        int seg = t2 % NSEG;
        int t3  = t2 / NSEG;
        int w   = t3 % Ww;
        int c   = t3 / Ww;
        int h0  = hq * 4;
        int ch0 = seg * CPG;

        // td: ((c*C + ch)*W + w)*H + h ; h innermost, 16B aligned (H%4==0)
        const float4* __restrict__ base =
            (const float4*)(td + ((size_t)(c * Cc + ch0) * Ww + w) * Hh + h0);

        float acc0 = 0.f, acc1 = 0.f, acc2 = 0.f, acc3 = 0.f;
        #pragma unroll 8
        for (int ch = 0; ch < CPG; ++ch) {
            float4 v = __ldg(base + ch * ch_stride4);
            float wv = s_w[ch0 + ch];
            acc0 = fmaf(v.x, wv, acc0);
            acc1 = fmaf(v.y, wv, acc1);
            acc2 = fmaf(v.z, wv, acc2);
            acc3 = fmaf(v.w, wv, acc3);
        }

        const float* M = cam + c * 16;
        float m00 = M[0], m01 = M[1], m03 = M[3];
        float m10 = M[4], m11 = M[5], m13 = M[7];

        float accs[4] = {acc0, acc1, acc2, acc3};
        #pragma unroll
        for (int k = 0; k < 4; ++k) {
            int h = h0 + k;
            int n = h * Ww + w;             // ravel order of (H, W)
            float x = lc[n];                // row 0 of logits_coordinates
            float y = lc[NPTS + n];         // row 1
            bool mv;
            if (mode == 1)      mv = ((const unsigned char*)mask)[n] != 0;
            else if (mode == 0) mv = ((const int*)mask)[n] != 0;
            else                mv = ((const float*)mask)[n] != 0.f;

            float c0 = fmaf(m00, x, fmaf(m01, y, m03));
            float c1 = fmaf(m10, x, fmaf(m11, y, m13));
            // (coord+100)/0.5 == (coord+100)*2 exactly; jnp.round = half-even
            int i0 = (int)rintf((c0 + 100.0f) * 2.0f);
            int i1 = (int)rintf((c1 + 100.0f) * 2.0f);
            if (mv && i0 >= 0 && i0 < SSZ && i1 >= 0 && i1 < SSZ) {
                int cell = i0 * SSZ + i1;
                atomicAdd(&g_sum[cell], accs[k]);   // partial dot; linear so OK
                if (seg == 0) atomicAdd(&g_cnt[cell], 1.0f);
            }
        }
    }

    // ---------------- Grid barrier (all CTAs resident) ----------------
    __threadfence();           // flush this thread's atomics device-wide
    __syncthreads();
    if (threadIdx.x == 0) {
        atomicAdd(&g_bar, 1u);
        while (*((volatile unsigned*)&g_bar) < gridDim.x) {
            __nanosleep(128);
        }
    }
    __syncthreads();
    __threadfence();           // acquire: see all CTAs' atomics

    // ---------------- Phase 2: finalize output + reset scratch ----------------
    float b = __ldg(bcls);
    for (int i = blockIdx.x * 256 + threadIdx.x; i < NQ; i += gridDim.x * 256) {
        float4 s = ((const float4*)g_sum)[i];
        float4 n = ((const float4*)g_cnt)[i];
        float4 o;
        o.x = s.x / fmaxf(n.x, 1.0f) + b;   // cnt==0 -> sum==0 -> b (matches ref)
        o.y = s.y / fmaxf(n.y, 1.0f) + b;
        o.z = s.z / fmaxf(n.z, 1.0f) + b;
        o.w = s.w / fmaxf(n.w, 1.0f) + b;
        ((float4*)out)[i] = o;
        float4 z = make_float4(0.f, 0.f, 0.f, 0.f);
        ((float4*)g_sum)[i] = z;
        ((float4*)g_cnt)[i] = z;
    }

    // Last CTA to finish phase 2 resets the barrier counters for next launch.
    if (threadIdx.x == 0) {
        __threadfence();
        if (atomicAdd(&g_bar2, 1u) + 1 == gridDim.x) {
            g_bar  = 0;
            g_bar2 = 0;
        }
    }
}

extern "C" void kernel_launch(void* const* d_in, const int* in_sizes, int n_in,
                              void* d_out, int out_size) {
    const float* td   = (const float*)d_in[0];  // (1,6,256,196,200) f32
    const float* cam  = (const float*)d_in[1];  // (1,6,4,4) f32
    const float* lc   = (const float*)d_in[2];  // (4,39200) f32
    const void*  mask = (const void*) d_in[3];  // (200,196) bool-ish
    const float* wcls = (const float*)d_in[4];  // (256,) f32
    const float* bcls = (const float*)d_in[5];  // () f32
    float* out = (float*)d_out;                 // (1,1,400,400) f32

    int dev = 0, sms = 148;
    cudaGetDevice(&dev);
    cudaDeviceGetAttribute(&sms, cudaDevAttrMultiProcessorCount, dev);
    int grid = sms * CTAS_PER_SM;   // co-residency guaranteed by launch_bounds

    fused_all_kernel<<<grid, 256>>>(td, cam, lc, mask, wcls, bcls, out);
}

// round 8
// speedup vs baseline: 1.1812x; 1.1812x over previous
#include <cuda_runtime.h>
#include <cstdint>

#define Hh 200
#define Ww 196
#define Cc 256
#define NCAMS 6
#define SSZ 400
#define NCELLS (SSZ*SSZ)
#define NPTS (Hh*Ww)     // 39200
#define HQ (Hh/4)        // 50
#define NSEG 4           // channel groups
#define CPG (Cc/NSEG)    // 64 channels per group
#define NTHREADS (NCAMS*Ww*NSEG*HQ)   // 235200 -> 919 CTAs of 256

// Interleaved accumulator: g_acc[2*cell] = sum, g_acc[2*cell+1] = count.
// Zero-initialized at module load; final_kernel resets it each launch so every
// launch / graph replay sees zeroed scratch (deterministic).
__device__ float g_acc[2 * NCELLS];

// One thread per (cam, w, chan-group, h-quad). Streams td_feats exactly once
// (coalesced float4 over innermost h), partial-dots 64 channels against s_w,
// then scatters the partial scalar per point (group 0 also bumps the count).
// Sum and count for a cell share one 32B sector (interleaved layout).
// Warp 0 fingerprints the mask dtype from its byte pattern (mask ~90% true):
//   int32 0/1  : low byte of words sometimes set, upper 3 bytes never
//   f32 0/1.0f : low byte never set, upper bytes sometimes (0x3f800000)
//   u8 bool    : both populated
__global__ void __launch_bounds__(256, 6) fused_dot_scatter_kernel(
    const float* __restrict__ td, const float* __restrict__ cam,
    const float* __restrict__ lc, const void*  __restrict__ mask,
    const float* __restrict__ wcls)
{
    __shared__ float s_w[Cc];
    __shared__ int   s_mode;

    if (threadIdx.x < 32) {
        const unsigned* mw = (const unsigned*)mask;
        unsigned lo = 0, hi = 0;
        #pragma unroll
        for (int k = 0; k < 3; ++k) {           // words 0..95 (384 B of mask)
            unsigned v = mw[threadIdx.x + 32 * k];
            lo |= (v & 0xFFu);
            hi |= (v & 0xFFFFFF00u);
        }
        unsigned any_lo = __ballot_sync(0xFFFFFFFF, lo != 0);
        unsigned any_hi = __ballot_sync(0xFFFFFFFF, hi != 0);
        if (threadIdx.x == 0) {
            int mode;
            if (any_lo && any_hi) mode = 1;     // u8 bool
            else if (any_lo)      mode = 0;     // int32
            else                  mode = 2;     // float32
            s_mode = mode;
        }
    }
    for (int i = threadIdx.x; i < Cc; i += blockDim.x) s_w[i] = wcls[i];
    __syncthreads();

    int tid = blockIdx.x * blockDim.x + threadIdx.x;
    if (tid >= NTHREADS) return;
    // hq innermost for coalescing, then chan-group, then w, then cam
    int hq  = tid % HQ;
    int t2  = tid / HQ;
    int seg = t2 % NSEG;
    int t3  = t2 / NSEG;
    int w   = t3 % Ww;
    int c   = t3 / Ww;
    int h0  = hq * 4;
    int ch0 = seg * CPG;

    // td flat index: ((c*C + ch)*W + w)*H + h ; h innermost, 16B aligned (H%4==0)
    const float4* __restrict__ base =
        (const float4*)(td + ((size_t)(c * Cc + ch0) * Ww + w) * Hh + h0);
    const int ch_stride4 = (Ww * Hh) / 4;   // 9800 float4 between channels

    float acc0 = 0.f, acc1 = 0.f, acc2 = 0.f, acc3 = 0.f;
    #pragma unroll 8
    for (int ch = 0; ch < CPG; ++ch) {
        float4 v = __ldg(base + ch * ch_stride4);
        float wv = s_w[ch0 + ch];
        acc0 = fmaf(v.x, wv, acc0);
        acc1 = fmaf(v.y, wv, acc1);
        acc2 = fmaf(v.z, wv, acc2);
        acc3 = fmaf(v.w, wv, acc3);
    }

    const float* M = cam + c * 16;
    float m00 = M[0], m01 = M[1], m03 = M[3];
    float m10 = M[4], m11 = M[5], m13 = M[7];
    int mode = s_mode;

    float accs[4] = {acc0, acc1, acc2, acc3};
    #pragma unroll
    for (int k = 0; k < 4; ++k) {
        int h = h0 + k;
        int n = h * Ww + w;               // ravel order of (H, W)
        float x = lc[n];                  // row 0 of logits_coordinates
        float y = lc[NPTS + n];           // row 1
        bool mv;
        if (mode == 1)      mv = ((const unsigned char*)mask)[n] != 0;
        else if (mode == 0) mv = ((const int*)mask)[n] != 0;
        else                mv = ((const float*)mask)[n] != 0.f;

        float c0 = fmaf(m00, x, fmaf(m01, y, m03));
        float c1 = fmaf(m10, x, fmaf(m11, y, m13));
        // (coord + 100)/0.5 == (coord + 100)*2 exactly; jnp.round = half-even = rintf
        int i0 = (int)rintf((c0 + 100.0f) * 2.0f);
        int i1 = (int)rintf((c1 + 100.0f) * 2.0f);
        if (mv && i0 >= 0 && i0 < SSZ && i1 >= 0 && i1 < SSZ) {
            int cell = i0 * SSZ + i1;
            atomicAdd(&g_acc[2 * cell], accs[k]);        // partial dot; linear so OK
            if (seg == 0) atomicAdd(&g_acc[2 * cell + 1], 1.0f);
        }
    }
}

// Consumes the interleaved accumulator (one float4 covers 2 cells' (sum,cnt))
// AND resets it to zero for the next launch.
__global__ void __launch_bounds__(256) final_kernel(float* __restrict__ out,
                                                    const float* __restrict__ bcls) {
    int i = blockIdx.x * blockDim.x + threadIdx.x;   // pair index: cells 2i, 2i+1
    if (i >= NCELLS / 2) return;
    float  b = __ldg(bcls);
    float4 v = ((const float4*)g_acc)[i];            // {sum0, cnt0, sum1, cnt1}
    float2 o;
    o.x = v.x / fmaxf(v.y, 1.0f) + b;   // cnt==0 -> sum==0 -> b (matches ref)
    o.y = v.z / fmaxf(v.w, 1.0f) + b;
    ((float2*)out)[i] = o;
    ((float4*)g_acc)[i] = make_float4(0.f, 0.f, 0.f, 0.f);
}

extern "C" void kernel_launch(void* const* d_in, const int* in_sizes, int n_in,
                              void* d_out, int out_size) {
    const float* td   = (const float*)d_in[0];  // (1,6,256,196,200) f32
    const float* cam  = (const float*)d_in[1];  // (1,6,4,4) f32
    const float* lc   = (const float*)d_in[2];  // (4,39200) f32
    const void*  mask = (const void*) d_in[3];  // (200,196) bool-ish
    const float* wcls = (const float*)d_in[4];  // (256,) f32
    const float* bcls = (const float*)d_in[5];  // () f32
    float* out = (float*)d_out;                 // (1,1,400,400) f32

    fused_dot_scatter_kernel<<<(NTHREADS + 255) / 256, 256>>>(td, cam, lc, mask, wcls);
    final_kernel<<<(NCELLS / 2 + 255) / 256, 256>>>(out, bcls);
}

// round 9
// speedup vs baseline: 1.2943x; 1.0958x over previous
#include <cuda_runtime.h>
#include <cstdint>

#define Hh 200
#define Ww 196
#define Cc 256
#define NCAMS 6
#define SSZ 400
#define NCELLS (SSZ*SSZ)
#define NPTS (Hh*Ww)     // 39200
#define HQ (Hh/4)        // 50
#define NSEG 4           // channel groups
#define CPG (Cc/NSEG)    // 64 channels per group
#define NTHREADS (NCAMS*Ww*NSEG*HQ)   // 235200 -> 919 CTAs of 256
#define NQ (NCELLS/4)

// Zero-initialized at module load; final_kernel resets sum/cnt each launch so
// every launch / graph replay sees zeroed scratch. g_cell is fully rewritten
// by cell_kernel each launch (deterministic).
__device__ float g_sum[NCELLS];
__device__ float g_cnt[NCELLS];
__device__ int   g_cell[NCAMS * NPTS];   // [cam][w*Hh + h] = cell or -1

// Precompute per (cam, point): projected cell index, with mask+bounds folded
// in, stored TRANSPOSED (h innermost) so the main kernel reads it coalesced.
// Thread = n (h*Ww+w order) -> lc/mask reads coalesced; writes scattered but
// fire-and-forget. Warp 0 of each block fingerprints the mask dtype
// (mask ~90% true) over the first 384 bytes:
//   int32 0/1 : low byte of words sometimes set, upper 3 bytes never
//   f32 0/1.0 : low byte never, upper bytes sometimes (0x3f800000)
//   u8 bool   : both populated
__global__ void __launch_bounds__(256) cell_kernel(
    const float* __restrict__ cam, const float* __restrict__ lc,
    const void* __restrict__ mask)
{
    __shared__ int s_mode;
    if (threadIdx.x < 32) {
        const unsigned* mw = (const unsigned*)mask;
        unsigned lo = 0, hi = 0;
        #pragma unroll
        for (int k = 0; k < 3; ++k) {
            unsigned v = mw[threadIdx.x + 32 * k];
            lo |= (v & 0xFFu);
            hi |= (v & 0xFFFFFF00u);
        }
        unsigned any_lo = __ballot_sync(0xFFFFFFFF, lo != 0);
        unsigned any_hi = __ballot_sync(0xFFFFFFFF, hi != 0);
        if (threadIdx.x == 0) {
            int mode;
            if (any_lo && any_hi) mode = 1;   // u8 bool
            else if (any_lo)      mode = 0;   // int32
            else                  mode = 2;   // float32
            s_mode = mode;
        }
    }
    __syncthreads();

    int n = blockIdx.x * blockDim.x + threadIdx.x;
    if (n >= NPTS) return;
    int mode = s_mode;

    float x = lc[n];                 // coalesced
    float y = lc[NPTS + n];
    bool mv;
    if (mode == 1)      mv = ((const unsigned char*)mask)[n] != 0;
    else if (mode == 0) mv = ((const int*)mask)[n] != 0;
    else                mv = ((const float*)mask)[n] != 0.f;

    int h = n / Ww;
    int w = n % Ww;

    #pragma unroll
    for (int c = 0; c < NCAMS; ++c) {
        const float* M = cam + c * 16;
        float c0 = fmaf(__ldg(M + 0), x, fmaf(__ldg(M + 1), y, __ldg(M + 3)));
        float c1 = fmaf(__ldg(M + 4), x, fmaf(__ldg(M + 5), y, __ldg(M + 7)));
        // (coord+100)/0.5 == (coord+100)*2 exactly; jnp.round = half-even = rintf
        int i0 = (int)rintf((c0 + 100.0f) * 2.0f);
        int i1 = (int)rintf((c1 + 100.0f) * 2.0f);
        int cell = (mv && i0 >= 0 && i0 < SSZ && i1 >= 0 && i1 < SSZ)
                     ? (i0 * SSZ + i1) : -1;
        g_cell[c * NPTS + w * Hh + h] = cell;   // transposed store
    }
}

// One thread per (cam, w, chan-group, h-quad). Streams td_feats exactly once
// (coalesced float4 over innermost h), partial-dots 64 channels against s_w,
// then reads its 4 precomputed cells with ONE coalesced int4 load and scatters
// the partial scalar per point (group 0 also bumps the count).
__global__ void __launch_bounds__(256) fused_dot_scatter_kernel(
    const float* __restrict__ td, const float* __restrict__ wcls)
{
    __shared__ float s_w[Cc];
    for (int i = threadIdx.x; i < Cc; i += blockDim.x) s_w[i] = wcls[i];
    __syncthreads();

    int tid = blockIdx.x * blockDim.x + threadIdx.x;
    if (tid >= NTHREADS) return;
    // hq innermost for coalescing, then chan-group, then w, then cam
    int hq  = tid % HQ;
    int t2  = tid / HQ;
    int seg = t2 % NSEG;
    int t3  = t2 / NSEG;
    int w   = t3 % Ww;
    int c   = t3 / Ww;
    int h0  = hq * 4;
    int ch0 = seg * CPG;

    // Issue the cell-table load FIRST so its latency hides under the channel loop.
    int4 cells = __ldg((const int4*)(g_cell + c * NPTS + w * Hh + h0));

    // td flat index: ((c*C + ch)*W + w)*H + h ; h innermost, 16B aligned (H%4==0)
    const float4* __restrict__ base =
        (const float4*)(td + ((size_t)(c * Cc + ch0) * Ww + w) * Hh + h0);
    const int ch_stride4 = (Ww * Hh) / 4;   // 9800 float4 between channels

    float acc0 = 0.f, acc1 = 0.f, acc2 = 0.f, acc3 = 0.f;
    #pragma unroll 8
    for (int ch = 0; ch < CPG; ++ch) {
        float4 v = __ldg(base + ch * ch_stride4);
        float wv = s_w[ch0 + ch];
        acc0 = fmaf(v.x, wv, acc0);
        acc1 = fmaf(v.y, wv, acc1);
        acc2 = fmaf(v.z, wv, acc2);
        acc3 = fmaf(v.w, wv, acc3);
    }

    float accs[4] = {acc0, acc1, acc2, acc3};
    int   cls[4]  = {cells.x, cells.y, cells.z, cells.w};
    #pragma unroll
    for (int k = 0; k < 4; ++k) {
        int cell = cls[k];
        if (cell >= 0) {
            atomicAdd(&g_sum[cell], accs[k]);      // partial dot; linear so OK
            if (seg == 0) atomicAdd(&g_cnt[cell], 1.0f);
        }
    }
}

// Consumes the accumulators AND resets them to zero for the next launch.
__global__ void __launch_bounds__(256) final_kernel(float* __restrict__ out,
                                                    const float* __restrict__ bcls) {
    int i = blockIdx.x * blockDim.x + threadIdx.x;
    if (i >= NQ) return;
    float  b = __ldg(bcls);
    float4 s = ((const float4*)g_sum)[i];
    float4 n = ((const float4*)g_cnt)[i];
    float4 o;
    o.x = s.x / fmaxf(n.x, 1.0f) + b;   // cnt==0 -> sum==0 -> b (matches ref)
    o.y = s.y / fmaxf(n.y, 1.0f) + b;
    o.z = s.z / fmaxf(n.z, 1.0f) + b;
    o.w = s.w / fmaxf(n.w, 1.0f) + b;
    ((float4*)out)[i] = o;
    float4 z = make_float4(0.f, 0.f, 0.f, 0.f);
    ((float4*)g_sum)[i] = z;
    ((float4*)g_cnt)[i] = z;
}

extern "C" void kernel_launch(void* const* d_in, const int* in_sizes, int n_in,
                              void* d_out, int out_size) {
    const float* td   = (const float*)d_in[0];  // (1,6,256,196,200) f32
    const float* cam  = (const float*)d_in[1];  // (1,6,4,4) f32
    const float* lc   = (const float*)d_in[2];  // (4,39200) f32
    const void*  mask = (const void*) d_in[3];  // (200,196) bool-ish
    const float* wcls = (const float*)d_in[4];  // (256,) f32
    const float* bcls = (const float*)d_in[5];  // () f32
    float* out = (float*)d_out;                 // (1,1,400,400) f32

    cell_kernel<<<(NPTS + 255) / 256, 256>>>(cam, lc, mask);
    fused_dot_scatter_kernel<<<(NTHREADS + 255) / 256, 256>>>(td, wcls);
    final_kernel<<<(NQ + 255) / 256, 256>>>(out, bcls);
}